// round 15
// baseline (speedup 1.0000x reference)
#include <cuda_runtime.h>
#include <cuda_fp16.h>
#include <cstdint>

#define N_ENT 50000
#define N_REL 500
#define N_TOT (N_ENT + N_REL)   // 50500
#define E_NUM 800000
#define D_IN  100
#define D_OUT 200
#define ALPHA 0.2f
#define EPSN  1e-12f

#define EMB_STRIDE 128   // halves per embh row (256B, line-aligned)
#define H1_STRIDE  256   // halves per h1h row (512B, line-aligned)

#define CSR_NBLK 148
#define CSR_THR  1024
#define CSR_SLICE ((N_TOT + CSR_NBLK - 1) / CSR_NBLK)   // 342

// ---------------- scratch (device globals; zero-initialized at load) -------
__device__ __half g_embh[N_TOT * EMB_STRIDE];
__device__ __half g_w1t[D_OUT * D_IN];
__device__ __half g_w2t[D_OUT * D_OUT];
__device__ __half g_bufh[N_TOT * D_OUT];
__device__ __half g_h1h[N_TOT * H1_STRIDE];
__device__ int    g_counts[N_TOT];        // zeroed at load; re-zeroed in scan phase
__device__ int    g_starts[N_TOT + 1];
__device__ int    g_rank[E_NUM];
__device__ int    g_bsum[CSR_NBLK];
__device__ unsigned g_bar_count;          // grid barrier state
__device__ unsigned g_bar_gen;
__device__ int2   g_edge[E_NUM];          // dst-sorted (src, val_bits fp32)

// ---------------- helpers ----------------
__device__ __forceinline__ void grid_barrier() {
    __threadfence();
    __syncthreads();
    if (threadIdx.x == 0) {
        unsigned gen = *((volatile unsigned*)&g_bar_gen);
        if (atomicAdd(&g_bar_count, 1u) == CSR_NBLK - 1) {
            g_bar_count = 0;
            __threadfence();
            *((volatile unsigned*)&g_bar_gen) = gen + 1;
        } else {
            while (*((volatile unsigned*)&g_bar_gen) == gen) { }
        }
        __threadfence();
    }
    __syncthreads();
}
__device__ __forceinline__ void mma_f16_k16(
    float& d0, float& d1, float& d2, float& d3,
    unsigned a0, unsigned a1, unsigned a2, unsigned a3,
    unsigned b0, unsigned b1,
    float c0, float c1, float c2, float c3) {
    asm("mma.sync.aligned.m16n8k16.row.col.f32.f16.f16.f32 "
        "{%0,%1,%2,%3},{%4,%5,%6,%7},{%8,%9},{%10,%11,%12,%13};"
        : "=f"(d0), "=f"(d1), "=f"(d2), "=f"(d3)
        : "r"(a0), "r"(a1), "r"(a2), "r"(a3), "r"(b0), "r"(b1),
          "f"(c0), "f"(c1), "f"(c2), "f"(c3));
}
__device__ __forceinline__ void mma_f16_k8(
    float& d0, float& d1, float& d2, float& d3,
    unsigned a0, unsigned a1, unsigned b0,
    float c0, float c1, float c2, float c3) {
    asm("mma.sync.aligned.m16n8k8.row.col.f32.f16.f16.f32 "
        "{%0,%1,%2,%3},{%4,%5},{%6},{%7,%8,%9,%10};"
        : "=f"(d0), "=f"(d1), "=f"(d2), "=f"(d3)
        : "r"(a0), "r"(a1), "r"(b0),
          "f"(c0), "f"(c1), "f"(c2), "f"(c3));
}
__device__ __forceinline__ void load_idx4(const void* ei, long long base, int e4,
                                          int is64, int d[4]) {
    if (is64) {
        const longlong2* p = (const longlong2*)ei;
        long long off = (base + 4LL * e4) >> 1;
        longlong2 a = __ldg(&p[off]);
        longlong2 b = __ldg(&p[off + 1]);
        d[0] = (int)a.x; d[1] = (int)a.y; d[2] = (int)b.x; d[3] = (int)b.y;
    } else {
        const int4* p = (const int4*)ei;
        int4 a = __ldg(&p[(base + 4LL * e4) >> 2]);
        d[0] = a.x; d[1] = a.y; d[2] = a.z; d[3] = a.w;
    }
}

// ======== persistent CSR kernel: hist+rank+convert | scan | scatter ========
__global__ void __launch_bounds__(CSR_THR)
csr_kernel(const void* __restrict__ ei, const float* __restrict__ ev,
           const float2* __restrict__ emb, const float* __restrict__ W1,
           const float* __restrict__ W2) {
    __shared__ int s_is64;
    __shared__ int woff[32];
    __shared__ int s_part[5];
    const int tid = threadIdx.x;
    const int lane = tid & 31;
    const int wid = tid >> 5;
    const int b = blockIdx.x;
    const int gtid = b * CSR_THR + tid;
    const int gstride = CSR_NBLK * CSR_THR;

    // dtype detect (per block)
    if (tid == 0) {
        const int* w = (const int*)ei;
        int f = 1;
        #pragma unroll 8
        for (int j = 1; j < 256; j += 2)
            if (w[j] != 0) f = 0;
        s_is64 = f;
    }
    __syncthreads();
    const int is64 = s_is64;

    // ---- Phase 1: histogram + ranks, fp16 conversions ----
    for (int e4 = gtid; e4 < E_NUM / 4; e4 += gstride) {
        int d[4];
        load_idx4(ei, E_NUM, e4, is64, d);
        int4 rk;
        rk.x = atomicAdd(&g_counts[d[0]], 1);
        rk.y = atomicAdd(&g_counts[d[1]], 1);
        rk.z = atomicAdd(&g_counts[d[2]], 1);
        rk.w = atomicAdd(&g_counts[d[3]], 1);
        ((int4*)g_rank)[e4] = rk;
    }
    {
        __half2* dst = (__half2*)g_embh;
        const int total2 = N_TOT * D_IN / 2;
        for (int k = gtid; k < total2; k += gstride) {
            int row = k / 50, col = k % 50;
            dst[row * (EMB_STRIDE / 2) + col] = __float22half2_rn(__ldg(&emb[k]));
        }
        for (int k = gtid; k < D_IN * D_OUT; k += gstride) {
            int kk = k / D_OUT, n = k % D_OUT;
            g_w1t[n * D_IN + kk] = __float2half_rn(__ldg(&W1[k]));
        }
        for (int k = gtid; k < D_OUT * D_OUT; k += gstride) {
            int kk = k / D_OUT, n = k % D_OUT;
            g_w2t[n * D_OUT + kk] = __float2half_rn(__ldg(&W2[k]));
        }
    }
    grid_barrier();

    // ---- Phase 2a: block-local exclusive scan of this block's slice ----
    const int i = b * CSR_SLICE + tid;          // tid may exceed slice; v=0 there
    const bool in_slice = (tid < CSR_SLICE) && (i < N_TOT);
    int v = in_slice ? g_counts[i] : 0;
    if (in_slice) g_counts[i] = 0;              // re-zero for next replay

    int incl = v;
    #pragma unroll
    for (int o = 1; o < 32; o <<= 1) {
        int t = __shfl_up_sync(0xffffffffu, incl, o);
        if (lane >= o) incl += t;
    }
    if (lane == 31) woff[wid] = incl;
    __syncthreads();
    if (wid == 0) {
        int w = woff[lane];
        int wincl = w;
        #pragma unroll
        for (int o = 1; o < 32; o <<= 1) {
            int t = __shfl_up_sync(0xffffffffu, wincl, o);
            if (lane >= o) wincl += t;
        }
        woff[lane] = wincl - w;                  // exclusive warp offsets
        if (lane == 31) g_bsum[b] = wincl;       // block total
    }
    __syncthreads();
    const int ex_in_block = woff[wid] + (incl - v);

    grid_barrier();

    // ---- Phase 2b: add prefix of preceding block sums, write starts ----
    if (tid < 160) {
        int p = (tid < b) ? g_bsum[tid] : 0;     // b <= 147 < 160
        #pragma unroll
        for (int o = 16; o; o >>= 1) p += __shfl_down_sync(0xffffffffu, p, o);
        if (lane == 0) s_part[tid >> 5] = p;
    }
    __syncthreads();
    const int off = s_part[0] + s_part[1] + s_part[2] + s_part[3] + s_part[4];
    if (in_slice) g_starts[i] = off + ex_in_block;
    if (b == 0 && tid == 0) g_starts[N_TOT] = E_NUM;

    grid_barrier();

    // ---- Phase 3: atomic-free scatter ----
    for (int e4 = gtid; e4 < E_NUM / 4; e4 += gstride) {
        int s[4], d[4];
        load_idx4(ei, 0, e4, is64, s);
        load_idx4(ei, E_NUM, e4, is64, d);
        int4 rk = __ldg(&((const int4*)g_rank)[e4]);
        float4 vv = __ldg(&((const float4*)ev)[e4]);
        int p0 = __ldg(&g_starts[d[0]]) + rk.x;
        int p1 = __ldg(&g_starts[d[1]]) + rk.y;
        int p2 = __ldg(&g_starts[d[2]]) + rk.z;
        int p3 = __ldg(&g_starts[d[3]]) + rk.w;
        g_edge[p0] = make_int2(s[0], __float_as_int(vv.x));
        g_edge[p1] = make_int2(s[1], __float_as_int(vv.y));
        g_edge[p2] = make_int2(s[2], __float_as_int(vv.z));
        g_edge[p3] = make_int2(s[3], __float_as_int(vv.w));
    }
}

// ---------------- agg1: bufh[r,0:100] = fp16( sum embh[src]*val ) ----------
__global__ void __launch_bounds__(256)
agg1_kernel(const uint2* __restrict__ h, __half* __restrict__ out, int nRows) {
    const int g = threadIdx.x >> 5;
    const int lane = threadIdx.x & 31;
    const int r = blockIdx.x * 8 + g;
    if (r >= nRows) return;
    const bool act = lane < 25;
    const int beg = g_starts[r];
    const int end = g_starts[r + 1];

    float acc[4] = {0.f, 0.f, 0.f, 0.f};
    int i = beg;
    for (; i + 3 < end; i += 4) {
        int2 e0 = __ldg(&g_edge[i]),     e1 = __ldg(&g_edge[i + 1]);
        int2 e2 = __ldg(&g_edge[i + 2]), e3 = __ldg(&g_edge[i + 3]);
        if (act) {
            uint2 u0 = __ldg(&h[(long long)e0.x * (EMB_STRIDE / 4) + lane]);
            uint2 u1 = __ldg(&h[(long long)e1.x * (EMB_STRIDE / 4) + lane]);
            uint2 u2 = __ldg(&h[(long long)e2.x * (EMB_STRIDE / 4) + lane]);
            uint2 u3 = __ldg(&h[(long long)e3.x * (EMB_STRIDE / 4) + lane]);
            float v0 = __int_as_float(e0.y), v1 = __int_as_float(e1.y);
            float v2 = __int_as_float(e2.y), v3 = __int_as_float(e3.y);
            float2 a0 = __half22float2(*(const __half2*)&u0.x);
            float2 b0 = __half22float2(*(const __half2*)&u0.y);
            float2 a1 = __half22float2(*(const __half2*)&u1.x);
            float2 b1 = __half22float2(*(const __half2*)&u1.y);
            float2 a2 = __half22float2(*(const __half2*)&u2.x);
            float2 b2 = __half22float2(*(const __half2*)&u2.y);
            float2 a3 = __half22float2(*(const __half2*)&u3.x);
            float2 b3 = __half22float2(*(const __half2*)&u3.y);
            acc[0] = fmaf(a0.x, v0, acc[0]); acc[1] = fmaf(a0.y, v0, acc[1]);
            acc[2] = fmaf(b0.x, v0, acc[2]); acc[3] = fmaf(b0.y, v0, acc[3]);
            acc[0] = fmaf(a1.x, v1, acc[0]); acc[1] = fmaf(a1.y, v1, acc[1]);
            acc[2] = fmaf(b1.x, v1, acc[2]); acc[3] = fmaf(b1.y, v1, acc[3]);
            acc[0] = fmaf(a2.x, v2, acc[0]); acc[1] = fmaf(a2.y, v2, acc[1]);
            acc[2] = fmaf(b2.x, v2, acc[2]); acc[3] = fmaf(b2.y, v2, acc[3]);
            acc[0] = fmaf(a3.x, v3, acc[0]); acc[1] = fmaf(a3.y, v3, acc[1]);
            acc[2] = fmaf(b3.x, v3, acc[2]); acc[3] = fmaf(b3.y, v3, acc[3]);
        }
    }
    for (; i < end; i++) {
        int2 e0 = __ldg(&g_edge[i]);
        if (act) {
            float v0 = __int_as_float(e0.y);
            uint2 u0 = __ldg(&h[(long long)e0.x * (EMB_STRIDE / 4) + lane]);
            float2 a0 = __half22float2(*(const __half2*)&u0.x);
            float2 b0 = __half22float2(*(const __half2*)&u0.y);
            acc[0] = fmaf(a0.x, v0, acc[0]); acc[1] = fmaf(a0.y, v0, acc[1]);
            acc[2] = fmaf(b0.x, v0, acc[2]); acc[3] = fmaf(b0.y, v0, acc[3]);
        }
    }
    if (act) {
        __half2 h0 = __float22half2_rn(make_float2(acc[0], acc[1]));
        __half2 h1 = __float22half2_rn(make_float2(acc[2], acc[3]));
        uint2 u = make_uint2(*(unsigned*)&h0, *(unsigned*)&h1);
        *(uint2*)&out[(long long)r * 100 + lane * 4] = u;
    }
}

// ---------------- aggH: bufh[r,0:200] = fp16( sum h1h[src]*val ) -----------
__global__ void __launch_bounds__(256)
aggH_kernel(const uint4* __restrict__ h, uint4* __restrict__ out, int nRows) {
    const int g = threadIdx.x >> 5;
    const int lane = threadIdx.x & 31;
    const int r = blockIdx.x * 8 + g;
    if (r >= nRows) return;
    const bool act = lane < 25;
    const int beg = g_starts[r];
    const int end = g_starts[r + 1];

    float acc[8];
    #pragma unroll
    for (int c = 0; c < 8; c++) acc[c] = 0.f;

    int i = beg;
    for (; i + 3 < end; i += 4) {
        int2 e0 = __ldg(&g_edge[i]),     e1 = __ldg(&g_edge[i + 1]);
        int2 e2 = __ldg(&g_edge[i + 2]), e3 = __ldg(&g_edge[i + 3]);
        if (act) {
            uint4 u0 = __ldg(&h[(long long)e0.x * (H1_STRIDE / 8) + lane]);
            uint4 u1 = __ldg(&h[(long long)e1.x * (H1_STRIDE / 8) + lane]);
            uint4 u2 = __ldg(&h[(long long)e2.x * (H1_STRIDE / 8) + lane]);
            uint4 u3 = __ldg(&h[(long long)e3.x * (H1_STRIDE / 8) + lane]);
            float v0 = __int_as_float(e0.y), v1 = __int_as_float(e1.y);
            float v2 = __int_as_float(e2.y), v3 = __int_as_float(e3.y);
            const unsigned* w0 = &u0.x;
            const unsigned* w1 = &u1.x;
            const unsigned* w2 = &u2.x;
            const unsigned* w3 = &u3.x;
            #pragma unroll
            for (int q = 0; q < 4; q++) {
                float2 f0 = __half22float2(*(const __half2*)&w0[q]);
                float2 f1 = __half22float2(*(const __half2*)&w1[q]);
                float2 f2 = __half22float2(*(const __half2*)&w2[q]);
                float2 f3 = __half22float2(*(const __half2*)&w3[q]);
                acc[q * 2]     = fmaf(f0.x, v0, acc[q * 2]);
                acc[q * 2 + 1] = fmaf(f0.y, v0, acc[q * 2 + 1]);
                acc[q * 2]     = fmaf(f1.x, v1, acc[q * 2]);
                acc[q * 2 + 1] = fmaf(f1.y, v1, acc[q * 2 + 1]);
                acc[q * 2]     = fmaf(f2.x, v2, acc[q * 2]);
                acc[q * 2 + 1] = fmaf(f2.y, v2, acc[q * 2 + 1]);
                acc[q * 2]     = fmaf(f3.x, v3, acc[q * 2]);
                acc[q * 2 + 1] = fmaf(f3.y, v3, acc[q * 2 + 1]);
            }
        }
    }
    for (; i < end; i++) {
        int2 e0 = __ldg(&g_edge[i]);
        if (act) {
            float v0 = __int_as_float(e0.y);
            uint4 u0 = __ldg(&h[(long long)e0.x * (H1_STRIDE / 8) + lane]);
            const unsigned* w0 = &u0.x;
            #pragma unroll
            for (int q = 0; q < 4; q++) {
                float2 f0 = __half22float2(*(const __half2*)&w0[q]);
                acc[q * 2]     = fmaf(f0.x, v0, acc[q * 2]);
                acc[q * 2 + 1] = fmaf(f0.y, v0, acc[q * 2 + 1]);
            }
        }
    }
    if (act) {
        uint4 u;
        __half2 p0 = __float22half2_rn(make_float2(acc[0], acc[1]));
        __half2 p1 = __float22half2_rn(make_float2(acc[2], acc[3]));
        __half2 p2 = __float22half2_rn(make_float2(acc[4], acc[5]));
        __half2 p3 = __float22half2_rn(make_float2(acc[6], acc[7]));
        u.x = *(unsigned*)&p0; u.y = *(unsigned*)&p1;
        u.z = *(unsigned*)&p2; u.w = *(unsigned*)&p3;
        out[(long long)r * 25 + lane] = u;
    }
}

// ---------------- fp16 HMMA GEMM: C = postproc(A_half @ Wt_half^T) ---------
#define CK 40
#define APAD 52
template <int K, int KP, int AS, int CS, bool LEAKY, bool NORM, bool HALF_OUT>
__global__ void __launch_bounds__(256)
gemm_f16_kernel(const __half* __restrict__ A, const __half* __restrict__ Wt,
                void* __restrict__ Cv, int nRows) {
    __shared__ __half a_s[64][APAD];
    __shared__ __half w_s[200][APAD];
    __shared__ float ssum[64][2];
    const int tid = threadIdx.x;
    const int wid = tid >> 5;
    const int lane = tid & 31;
    const int grp = lane >> 2;
    const int tig = lane & 3;
    const int wm = wid & 3;
    const int wn = wid >> 2;
    const int jbase = wn ? 13 : 0;
    const int jcount = wn ? 12 : 13;
    const int r0 = blockIdx.x * 64;

    float acc[13][4];
    #pragma unroll
    for (int j = 0; j < 13; j++)
        #pragma unroll
        for (int c = 0; c < 4; c++) acc[j][c] = 0.f;

    #pragma unroll
    for (int ch = 0; ch < KP / CK; ch++) {
        const int k0 = ch * CK;
        #pragma unroll
        for (int i = 0; i < 3; i++) {
            int idx4 = tid + i * 256;
            if (idx4 < 640) {
                int row = idx4 / 10;
                int q = idx4 % 10;
                int gr = r0 + row;
                uint2 u = make_uint2(0u, 0u);
                if (gr < nRows && k0 + q * 4 < K)
                    u = *(const uint2*)&A[(long long)gr * AS + k0 + q * 4];
                *(uint2*)&a_s[row][q * 4] = u;
            }
        }
        #pragma unroll
        for (int i = 0; i < 8; i++) {
            int idx4 = tid + i * 256;
            if (idx4 < 2000) {
                int n = idx4 / 10;
                int q = idx4 % 10;
                uint2 u = make_uint2(0u, 0u);
                if (k0 + q * 4 < K)
                    u = *(const uint2*)&Wt[(long long)n * K + k0 + q * 4];
                *(uint2*)&w_s[n][q * 4] = u;
            }
        }
        __syncthreads();

        const int arow = wm * 16 + grp;
        #pragma unroll
        for (int ks = 0; ks < 2; ks++) {
            const int kk = ks * 16;
            unsigned a0 = *(const unsigned*)&a_s[arow][kk + 2 * tig];
            unsigned a1 = *(const unsigned*)&a_s[arow + 8][kk + 2 * tig];
            unsigned a2 = *(const unsigned*)&a_s[arow][kk + 2 * tig + 8];
            unsigned a3 = *(const unsigned*)&a_s[arow + 8][kk + 2 * tig + 8];
            #pragma unroll
            for (int j = 0; j < 13; j++) {
                if (j < jcount) {
                    int n = (jbase + j) * 8 + grp;
                    unsigned b0 = *(const unsigned*)&w_s[n][kk + 2 * tig];
                    unsigned b1 = *(const unsigned*)&w_s[n][kk + 2 * tig + 8];
                    mma_f16_k16(acc[j][0], acc[j][1], acc[j][2], acc[j][3],
                                a0, a1, a2, a3, b0, b1,
                                acc[j][0], acc[j][1], acc[j][2], acc[j][3]);
                }
            }
        }
        {
            unsigned a0 = *(const unsigned*)&a_s[arow][32 + 2 * tig];
            unsigned a1 = *(const unsigned*)&a_s[arow + 8][32 + 2 * tig];
            #pragma unroll
            for (int j = 0; j < 13; j++) {
                if (j < jcount) {
                    int n = (jbase + j) * 8 + grp;
                    unsigned b0 = *(const unsigned*)&w_s[n][32 + 2 * tig];
                    mma_f16_k8(acc[j][0], acc[j][1], acc[j][2], acc[j][3],
                               a0, a1, b0,
                               acc[j][0], acc[j][1], acc[j][2], acc[j][3]);
                }
            }
        }
        __syncthreads();
    }

    if (LEAKY || NORM) {
        #pragma unroll
        for (int j = 0; j < 13; j++) {
            if (j < jcount) {
                #pragma unroll
                for (int c = 0; c < 4; c++)
                    acc[j][c] = acc[j][c] > 0.f ? acc[j][c] : ALPHA * acc[j][c];
            }
        }
    }
    float inv_lo = 1.f, inv_hi = 1.f;
    if (NORM) {
        float slo = 0.f, shi = 0.f;
        #pragma unroll
        for (int j = 0; j < 13; j++) {
            if (j < jcount) {
                slo = fmaf(acc[j][0], acc[j][0], slo);
                slo = fmaf(acc[j][1], acc[j][1], slo);
                shi = fmaf(acc[j][2], acc[j][2], shi);
                shi = fmaf(acc[j][3], acc[j][3], shi);
            }
        }
        #pragma unroll
        for (int o = 1; o <= 2; o <<= 1) {
            slo += __shfl_xor_sync(0xffffffffu, slo, o);
            shi += __shfl_xor_sync(0xffffffffu, shi, o);
        }
        if (tig == 0) {
            ssum[wm * 16 + grp][wn] = slo;
            ssum[wm * 16 + grp + 8][wn] = shi;
        }
        __syncthreads();
        float tlo = ssum[wm * 16 + grp][0] + ssum[wm * 16 + grp][1];
        float thi = ssum[wm * 16 + grp + 8][0] + ssum[wm * 16 + grp + 8][1];
        inv_lo = 1.0f / fmaxf(sqrtf(tlo), EPSN);
        inv_hi = 1.0f / fmaxf(sqrtf(thi), EPSN);
    }

    const int row_lo = r0 + wm * 16 + grp;
    const int row_hi = row_lo + 8;
    #pragma unroll
    for (int j = 0; j < 13; j++) {
        if (j < jcount) {
            int col = (jbase + j) * 8 + tig * 2;
            float o0 = acc[j][0] * inv_lo, o1 = acc[j][1] * inv_lo;
            float o2 = acc[j][2] * inv_hi, o3 = acc[j][3] * inv_hi;
            if (HALF_OUT) {
                __half* C = (__half*)Cv;
                __half2 plo = __float22half2_rn(make_float2(o0, o1));
                __half2 phi = __float22half2_rn(make_float2(o2, o3));
                if (row_lo < nRows) *(__half2*)&C[(long long)row_lo * CS + col] = plo;
                if (row_hi < nRows) *(__half2*)&C[(long long)row_hi * CS + col] = phi;
            } else {
                float* C = (float*)Cv;
                if (row_lo < nRows) *(float2*)&C[(long long)row_lo * CS + col] = make_float2(o0, o1);
                if (row_hi < nRows) *(float2*)&C[(long long)row_hi * CS + col] = make_float2(o2, o3);
            }
        }
    }
}

// ---------------- launch ----------------
extern "C" void kernel_launch(void* const* d_in, const int* in_sizes, int n_in,
                              void* d_out, int out_size) {
    const float* emb = (const float*)d_in[0];        // [N_TOT, 100]
    const float* W1  = (const float*)d_in[1];        // [100, 200]
    const float* W2  = (const float*)d_in[2];        // [200, 200]
    const void*  ei  = d_in[3];                      // [2, E]
    const float* ev  = (const float*)d_in[4];        // [E]
    float* out = (float*)d_out;                      // [N_TOT, 200]

    __half* embh; cudaGetSymbolAddress((void**)&embh, g_embh);
    __half* w1t;  cudaGetSymbolAddress((void**)&w1t, g_w1t);
    __half* w2t;  cudaGetSymbolAddress((void**)&w2t, g_w2t);
    __half* bufh; cudaGetSymbolAddress((void**)&bufh, g_bufh);
    __half* h1h;  cudaGetSymbolAddress((void**)&h1h, g_h1h);

    // CSR build + conversions: ONE persistent grid-synced kernel
    csr_kernel<<<CSR_NBLK, CSR_THR>>>(ei, ev, (const float2*)emb, W1, W2);

    int ggrid = (N_TOT + 63) / 64;

    // Layer 1: agg(emb fp16 padded) -> bufh; gemm1(+leaky) -> h1h (padded)
    agg1_kernel<<<(N_TOT + 7) / 8, 256>>>((const uint2*)embh, bufh, N_TOT);
    gemm_f16_kernel<D_IN, 120, D_IN, H1_STRIDE, true, false, true>
        <<<ggrid, 256>>>(bufh, w1t, h1h, N_TOT);

    // Layer 2: agg(h1h padded) -> bufh; gemm2(+leaky+norm) -> d_out
    aggH_kernel<<<(N_TOT + 7) / 8, 256>>>((const uint4*)h1h, (uint4*)bufh, N_TOT);
    gemm_f16_kernel<D_OUT, 200, D_OUT, D_OUT, true, true, false>
        <<<ggrid, 256>>>(bufh, w2t, out, N_TOT);
}

// round 16
// speedup vs baseline: 1.0098x; 1.0098x over previous
#include <cuda_runtime.h>
#include <cuda_fp16.h>
#include <cstdint>

#define N_ENT 50000
#define N_REL 500
#define N_TOT (N_ENT + N_REL)   // 50500
#define E_NUM 800000
#define D_IN  100
#define D_OUT 200
#define ALPHA 0.2f
#define EPSN  1e-12f

#define SCAN_BLK 1024
#define SCAN_NB  ((N_TOT + SCAN_BLK - 1) / SCAN_BLK)   // 50

// ---------------- scratch (device globals; zero-initialized at load) -------
__device__ __half g_embh[N_TOT * D_IN];   // fp16 embeddings
__device__ __half g_w1t[D_OUT * D_IN];    // W1^T fp16: [200][100]
__device__ __half g_w2t[D_OUT * D_OUT];   // W2^T fp16: [200][200]
__device__ __half g_bufh[N_TOT * D_OUT];  // agg1 out [N,100] / aggH out [N,200]
__device__ __half g_h1h[N_TOT * D_OUT];   // layer-1 output [N,200]
__device__ int    g_counts[N_TOT];        // zeroed at load; re-zeroed by scan
__device__ int    g_starts[N_TOT + 1];
__device__ int    g_rank[E_NUM];          // edge rank within its dst bucket
__device__ int    g_bsum[SCAN_NB];
__device__ int    g_flag[SCAN_NB];        // lookback flags; reset by hist blk0
__device__ int2   g_edge[E_NUM];          // dst-sorted (src, val_bits fp32)

// ---------------- helpers ----------------
__device__ __forceinline__ int detect_is64_block(const int* ei_words) {
    __shared__ int s_is64;
    if (threadIdx.x == 0) {
        int f = 1;
        #pragma unroll 8
        for (int j = 1; j < 256; j += 2)
            if (ei_words[j] != 0) f = 0;
        s_is64 = f;
    }
    __syncthreads();
    return s_is64;
}
__device__ __forceinline__ void mma_f16_k16(
    float& d0, float& d1, float& d2, float& d3,
    unsigned a0, unsigned a1, unsigned a2, unsigned a3,
    unsigned b0, unsigned b1,
    float c0, float c1, float c2, float c3) {
    asm("mma.sync.aligned.m16n8k16.row.col.f32.f16.f16.f32 "
        "{%0,%1,%2,%3},{%4,%5,%6,%7},{%8,%9},{%10,%11,%12,%13};"
        : "=f"(d0), "=f"(d1), "=f"(d2), "=f"(d3)
        : "r"(a0), "r"(a1), "r"(a2), "r"(a3), "r"(b0), "r"(b1),
          "f"(c0), "f"(c1), "f"(c2), "f"(c3));
}
__device__ __forceinline__ void mma_f16_k8(
    float& d0, float& d1, float& d2, float& d3,
    unsigned a0, unsigned a1, unsigned b0,
    float c0, float c1, float c2, float c3) {
    asm("mma.sync.aligned.m16n8k8.row.col.f32.f16.f16.f32 "
        "{%0,%1,%2,%3},{%4,%5},{%6},{%7,%8,%9,%10};"
        : "=f"(d0), "=f"(d1), "=f"(d2), "=f"(d3)
        : "r"(a0), "r"(a1), "r"(b0),
          "f"(c0), "f"(c1), "f"(c2), "f"(c3));
}
// load 8 consecutive edge indices starting at element base+8*e8
__device__ __forceinline__ void load_idx8(const void* ei, long long base, int e8,
                                          int is64, int d[8]) {
    if (is64) {
        const longlong2* p = (const longlong2*)ei;
        long long off = (base + 8LL * e8) >> 1;
        longlong2 a = __ldg(&p[off]);
        longlong2 b = __ldg(&p[off + 1]);
        longlong2 c = __ldg(&p[off + 2]);
        longlong2 e = __ldg(&p[off + 3]);
        d[0] = (int)a.x; d[1] = (int)a.y; d[2] = (int)b.x; d[3] = (int)b.y;
        d[4] = (int)c.x; d[5] = (int)c.y; d[6] = (int)e.x; d[7] = (int)e.y;
    } else {
        const int4* p = (const int4*)ei;
        long long off = (base + 8LL * e8) >> 2;
        int4 a = __ldg(&p[off]);
        int4 b = __ldg(&p[off + 1]);
        d[0] = a.x; d[1] = a.y; d[2] = a.z; d[3] = a.w;
        d[4] = b.x; d[5] = b.y; d[6] = b.z; d[7] = b.w;
    }
}

// ---------------- hist: 8 edges/thread; count + record per-edge rank -------
__global__ void __launch_bounds__(256)
hist_kernel(const void* __restrict__ ei) {
    int is64 = detect_is64_block((const int*)ei);
    if (blockIdx.x == 0 && threadIdx.x < SCAN_NB) g_flag[threadIdx.x] = 0;
    int e8 = blockIdx.x * blockDim.x + threadIdx.x;
    if (e8 < E_NUM / 8) {
        int d[8];
        load_idx8(ei, E_NUM, e8, is64, d);
        int rk[8];
        #pragma unroll
        for (int q = 0; q < 8; q++)
            rk[q] = atomicAdd(&g_counts[d[q]], 1);
        int4* rp = (int4*)g_rank;
        rp[e8 * 2]     = make_int4(rk[0], rk[1], rk[2], rk[3]);
        rp[e8 * 2 + 1] = make_int4(rk[4], rk[5], rk[6], rk[7]);
    }
}

// ------- scan (decoupled lookback) + fp16 conversions (emb, W1^T, W2^T) ----
__global__ void __launch_bounds__(SCAN_BLK)
scan_kernel(const float2* __restrict__ emb, const float* __restrict__ W1,
            const float* __restrict__ W2) {
    __shared__ int woff[32];
    __shared__ int s_off[2];
    const int tid = threadIdx.x;
    const int lane = tid & 31;
    const int wid = tid >> 5;
    const int b = blockIdx.x;
    const int i = b * SCAN_BLK + tid;

    int v = (i < N_TOT) ? g_counts[i] : 0;
    if (i < N_TOT) g_counts[i] = 0;        // re-zero for next replay

    int incl = v;
    #pragma unroll
    for (int o = 1; o < 32; o <<= 1) {
        int t = __shfl_up_sync(0xffffffffu, incl, o);
        if (lane >= o) incl += t;
    }
    if (lane == 31) woff[wid] = incl;
    __syncthreads();
    if (wid == 0) {
        int w = woff[lane];
        int wincl = w;
        #pragma unroll
        for (int o = 1; o < 32; o <<= 1) {
            int t = __shfl_up_sync(0xffffffffu, wincl, o);
            if (lane >= o) wincl += t;
        }
        woff[lane] = wincl - w;
        if (lane == 31) {
            g_bsum[b] = wincl;
            __threadfence();
            atomicExch(&g_flag[b], 1);
        }
    }
    __syncthreads();

    if (tid < 64) {
        int offv = 0;
        if (tid < b) {
            while (atomicAdd(&g_flag[tid], 0) == 0) { }
            __threadfence();
            offv = g_bsum[tid];
        }
        #pragma unroll
        for (int o = 16; o; o >>= 1) offv += __shfl_down_sync(0xffffffffu, offv, o);
        if ((tid & 31) == 0) s_off[tid >> 5] = offv;
    }
    __syncthreads();
    int off = s_off[0] + s_off[1];

    if (i < N_TOT) g_starts[i] = off + woff[wid] + (incl - v);
    if (b == SCAN_NB - 1 && tid == 0)
        g_starts[N_TOT] = off + g_bsum[b];

    // streaming fp16 conversions on the mostly-idle chip
    const int gtid = b * SCAN_BLK + tid;
    const int stride = SCAN_NB * SCAN_BLK;
    __half2* dst = (__half2*)g_embh;
    const int total2 = N_TOT * D_IN / 2;
    for (int k = gtid; k < total2; k += stride)
        dst[k] = __float22half2_rn(__ldg(&emb[k]));
    for (int k = gtid; k < D_IN * D_OUT; k += stride) {
        int kk = k / D_OUT, n = k % D_OUT;
        g_w1t[n * D_IN + kk] = __float2half_rn(__ldg(&W1[k]));
    }
    for (int k = gtid; k < D_OUT * D_OUT; k += stride) {
        int kk = k / D_OUT, n = k % D_OUT;
        g_w2t[n * D_OUT + kk] = __float2half_rn(__ldg(&W2[k]));
    }
}

// ---------------- scatter: 8 edges/thread, atomic-free via ranks -----------
__global__ void __launch_bounds__(256)
scatter_kernel(const void* __restrict__ ei, const float* __restrict__ ev) {
    int is64 = detect_is64_block((const int*)ei);
    int e8 = blockIdx.x * blockDim.x + threadIdx.x;
    if (e8 < E_NUM / 8) {
        int s[8], d[8];
        load_idx8(ei, 0, e8, is64, s);
        load_idx8(ei, E_NUM, e8, is64, d);
        const int4* rp = (const int4*)g_rank;
        int4 ra = __ldg(&rp[e8 * 2]);
        int4 rb = __ldg(&rp[e8 * 2 + 1]);
        int rk[8] = {ra.x, ra.y, ra.z, ra.w, rb.x, rb.y, rb.z, rb.w};
        float4 va = __ldg(&((const float4*)ev)[e8 * 2]);
        float4 vb = __ldg(&((const float4*)ev)[e8 * 2 + 1]);
        float vv[8] = {va.x, va.y, va.z, va.w, vb.x, vb.y, vb.z, vb.w};
        int pos[8];
        #pragma unroll
        for (int q = 0; q < 8; q++)
            pos[q] = __ldg(&g_starts[d[q]]) + rk[q];
        #pragma unroll
        for (int q = 0; q < 8; q++)
            g_edge[pos[q]] = make_int2(s[q], __float_as_int(vv[q]));
    }
}

// ---------------- agg1: bufh[r,0:100] = fp16( sum embh[src]*val ) ----------
// 1 row/warp; lanes 0..24 gather uint2 = 4 halves; fp32 accumulate.
__global__ void __launch_bounds__(256)
agg1_kernel(const uint2* __restrict__ h, __half* __restrict__ out, int nRows) {
    const int g = threadIdx.x >> 5;
    const int lane = threadIdx.x & 31;
    const int r = blockIdx.x * 8 + g;
    if (r >= nRows) return;
    const bool act = lane < 25;
    const int beg = g_starts[r];
    const int end = g_starts[r + 1];

    float acc[4] = {0.f, 0.f, 0.f, 0.f};
    int i = beg;
    for (; i + 3 < end; i += 4) {
        int2 e0 = __ldg(&g_edge[i]),     e1 = __ldg(&g_edge[i + 1]);
        int2 e2 = __ldg(&g_edge[i + 2]), e3 = __ldg(&g_edge[i + 3]);
        if (act) {
            uint2 u0 = __ldg(&h[(long long)e0.x * 25 + lane]);
            uint2 u1 = __ldg(&h[(long long)e1.x * 25 + lane]);
            uint2 u2 = __ldg(&h[(long long)e2.x * 25 + lane]);
            uint2 u3 = __ldg(&h[(long long)e3.x * 25 + lane]);
            float v0 = __int_as_float(e0.y), v1 = __int_as_float(e1.y);
            float v2 = __int_as_float(e2.y), v3 = __int_as_float(e3.y);
            float2 a0 = __half22float2(*(const __half2*)&u0.x);
            float2 b0 = __half22float2(*(const __half2*)&u0.y);
            float2 a1 = __half22float2(*(const __half2*)&u1.x);
            float2 b1 = __half22float2(*(const __half2*)&u1.y);
            float2 a2 = __half22float2(*(const __half2*)&u2.x);
            float2 b2 = __half22float2(*(const __half2*)&u2.y);
            float2 a3 = __half22float2(*(const __half2*)&u3.x);
            float2 b3 = __half22float2(*(const __half2*)&u3.y);
            acc[0] = fmaf(a0.x, v0, acc[0]); acc[1] = fmaf(a0.y, v0, acc[1]);
            acc[2] = fmaf(b0.x, v0, acc[2]); acc[3] = fmaf(b0.y, v0, acc[3]);
            acc[0] = fmaf(a1.x, v1, acc[0]); acc[1] = fmaf(a1.y, v1, acc[1]);
            acc[2] = fmaf(b1.x, v1, acc[2]); acc[3] = fmaf(b1.y, v1, acc[3]);
            acc[0] = fmaf(a2.x, v2, acc[0]); acc[1] = fmaf(a2.y, v2, acc[1]);
            acc[2] = fmaf(b2.x, v2, acc[2]); acc[3] = fmaf(b2.y, v2, acc[3]);
            acc[0] = fmaf(a3.x, v3, acc[0]); acc[1] = fmaf(a3.y, v3, acc[1]);
            acc[2] = fmaf(b3.x, v3, acc[2]); acc[3] = fmaf(b3.y, v3, acc[3]);
        }
    }
    for (; i < end; i++) {
        int2 e0 = __ldg(&g_edge[i]);
        if (act) {
            float v0 = __int_as_float(e0.y);
            uint2 u0 = __ldg(&h[(long long)e0.x * 25 + lane]);
            float2 a0 = __half22float2(*(const __half2*)&u0.x);
            float2 b0 = __half22float2(*(const __half2*)&u0.y);
            acc[0] = fmaf(a0.x, v0, acc[0]); acc[1] = fmaf(a0.y, v0, acc[1]);
            acc[2] = fmaf(b0.x, v0, acc[2]); acc[3] = fmaf(b0.y, v0, acc[3]);
        }
    }
    if (act) {
        __half2 h0 = __float22half2_rn(make_float2(acc[0], acc[1]));
        __half2 h1 = __float22half2_rn(make_float2(acc[2], acc[3]));
        uint2 u = make_uint2(*(unsigned*)&h0, *(unsigned*)&h1);
        *(uint2*)&out[(long long)r * 100 + lane * 4] = u;
    }
}

// ---------------- aggH: bufh[r,0:200] = fp16( sum h1h[src]*val ) -----------
__global__ void __launch_bounds__(256)
aggH_kernel(const uint4* __restrict__ h, uint4* __restrict__ out, int nRows) {
    const int g = threadIdx.x >> 5;
    const int lane = threadIdx.x & 31;
    const int r = blockIdx.x * 8 + g;
    if (r >= nRows) return;
    const bool act = lane < 25;
    const int beg = g_starts[r];
    const int end = g_starts[r + 1];

    float acc[8];
    #pragma unroll
    for (int c = 0; c < 8; c++) acc[c] = 0.f;

    int i = beg;
    for (; i + 3 < end; i += 4) {
        int2 e0 = __ldg(&g_edge[i]),     e1 = __ldg(&g_edge[i + 1]);
        int2 e2 = __ldg(&g_edge[i + 2]), e3 = __ldg(&g_edge[i + 3]);
        if (act) {
            uint4 u0 = __ldg(&h[(long long)e0.x * 25 + lane]);
            uint4 u1 = __ldg(&h[(long long)e1.x * 25 + lane]);
            uint4 u2 = __ldg(&h[(long long)e2.x * 25 + lane]);
            uint4 u3 = __ldg(&h[(long long)e3.x * 25 + lane]);
            float v0 = __int_as_float(e0.y), v1 = __int_as_float(e1.y);
            float v2 = __int_as_float(e2.y), v3 = __int_as_float(e3.y);
            const unsigned* w0 = &u0.x;
            const unsigned* w1 = &u1.x;
            const unsigned* w2 = &u2.x;
            const unsigned* w3 = &u3.x;
            #pragma unroll
            for (int q = 0; q < 4; q++) {
                float2 f0 = __half22float2(*(const __half2*)&w0[q]);
                float2 f1 = __half22float2(*(const __half2*)&w1[q]);
                float2 f2 = __half22float2(*(const __half2*)&w2[q]);
                float2 f3 = __half22float2(*(const __half2*)&w3[q]);
                acc[q * 2]     = fmaf(f0.x, v0, acc[q * 2]);
                acc[q * 2 + 1] = fmaf(f0.y, v0, acc[q * 2 + 1]);
                acc[q * 2]     = fmaf(f1.x, v1, acc[q * 2]);
                acc[q * 2 + 1] = fmaf(f1.y, v1, acc[q * 2 + 1]);
                acc[q * 2]     = fmaf(f2.x, v2, acc[q * 2]);
                acc[q * 2 + 1] = fmaf(f2.y, v2, acc[q * 2 + 1]);
                acc[q * 2]     = fmaf(f3.x, v3, acc[q * 2]);
                acc[q * 2 + 1] = fmaf(f3.y, v3, acc[q * 2 + 1]);
            }
        }
    }
    for (; i < end; i++) {
        int2 e0 = __ldg(&g_edge[i]);
        if (act) {
            float v0 = __int_as_float(e0.y);
            uint4 u0 = __ldg(&h[(long long)e0.x * 25 + lane]);
            const unsigned* w0 = &u0.x;
            #pragma unroll
            for (int q = 0; q < 4; q++) {
                float2 f0 = __half22float2(*(const __half2*)&w0[q]);
                acc[q * 2]     = fmaf(f0.x, v0, acc[q * 2]);
                acc[q * 2 + 1] = fmaf(f0.y, v0, acc[q * 2 + 1]);
            }
        }
    }
    if (act) {
        uint4 u;
        __half2 p0 = __float22half2_rn(make_float2(acc[0], acc[1]));
        __half2 p1 = __float22half2_rn(make_float2(acc[2], acc[3]));
        __half2 p2 = __float22half2_rn(make_float2(acc[4], acc[5]));
        __half2 p3 = __float22half2_rn(make_float2(acc[6], acc[7]));
        u.x = *(unsigned*)&p0; u.y = *(unsigned*)&p1;
        u.z = *(unsigned*)&p2; u.w = *(unsigned*)&p3;
        out[(long long)r * 25 + lane] = u;
    }
}

// ---------------- fp16 HMMA GEMM: C = postproc(A_half @ Wt_half^T) ---------
#define CK 40
#define APAD 52
template <int K, int KP, bool LEAKY, bool NORM, bool HALF_OUT>
__global__ void __launch_bounds__(256)
gemm_f16_kernel(const __half* __restrict__ A, const __half* __restrict__ Wt,
                void* __restrict__ Cv, int nRows) {
    __shared__ __half a_s[64][APAD];
    __shared__ __half w_s[200][APAD];
    __shared__ float ssum[64][2];
    const int tid = threadIdx.x;
    const int wid = tid >> 5;
    const int lane = tid & 31;
    const int grp = lane >> 2;
    const int tig = lane & 3;
    const int wm = wid & 3;
    const int wn = wid >> 2;
    const int jbase = wn ? 13 : 0;
    const int jcount = wn ? 12 : 13;
    const int r0 = blockIdx.x * 64;

    float acc[13][4];
    #pragma unroll
    for (int j = 0; j < 13; j++)
        #pragma unroll
        for (int c = 0; c < 4; c++) acc[j][c] = 0.f;

    #pragma unroll
    for (int ch = 0; ch < KP / CK; ch++) {
        const int k0 = ch * CK;
        #pragma unroll
        for (int i = 0; i < 3; i++) {
            int idx4 = tid + i * 256;
            if (idx4 < 640) {
                int row = idx4 / 10;
                int q = idx4 % 10;
                int gr = r0 + row;
                uint2 u = make_uint2(0u, 0u);
                if (gr < nRows && k0 + q * 4 < K)
                    u = *(const uint2*)&A[(long long)gr * K + k0 + q * 4];
                *(uint2*)&a_s[row][q * 4] = u;
            }
        }
        #pragma unroll
        for (int i = 0; i < 8; i++) {
            int idx4 = tid + i * 256;
            if (idx4 < 2000) {
                int n = idx4 / 10;
                int q = idx4 % 10;
                uint2 u = make_uint2(0u, 0u);
                if (k0 + q * 4 < K)
                    u = *(const uint2*)&Wt[(long long)n * K + k0 + q * 4];
                *(uint2*)&w_s[n][q * 4] = u;
            }
        }
        __syncthreads();

        const int arow = wm * 16 + grp;
        #pragma unroll
        for (int ks = 0; ks < 2; ks++) {
            const int kk = ks * 16;
            unsigned a0 = *(const unsigned*)&a_s[arow][kk + 2 * tig];
            unsigned a1 = *(const unsigned*)&a_s[arow + 8][kk + 2 * tig];
            unsigned a2 = *(const unsigned*)&a_s[arow][kk + 2 * tig + 8];
            unsigned a3 = *(const unsigned*)&a_s[arow + 8][kk + 2 * tig + 8];
            #pragma unroll
            for (int j = 0; j < 13; j++) {
                if (j < jcount) {
                    int n = (jbase + j) * 8 + grp;
                    unsigned b0 = *(const unsigned*)&w_s[n][kk + 2 * tig];
                    unsigned b1 = *(const unsigned*)&w_s[n][kk + 2 * tig + 8];
                    mma_f16_k16(acc[j][0], acc[j][1], acc[j][2], acc[j][3],
                                a0, a1, a2, a3, b0, b1,
                                acc[j][0], acc[j][1], acc[j][2], acc[j][3]);
                }
            }
        }
        {
            unsigned a0 = *(const unsigned*)&a_s[arow][32 + 2 * tig];
            unsigned a1 = *(const unsigned*)&a_s[arow + 8][32 + 2 * tig];
            #pragma unroll
            for (int j = 0; j < 13; j++) {
                if (j < jcount) {
                    int n = (jbase + j) * 8 + grp;
                    unsigned b0 = *(const unsigned*)&w_s[n][32 + 2 * tig];
                    mma_f16_k8(acc[j][0], acc[j][1], acc[j][2], acc[j][3],
                               a0, a1, b0,
                               acc[j][0], acc[j][1], acc[j][2], acc[j][3]);
                }
            }
        }
        __syncthreads();
    }

    if (LEAKY || NORM) {
        #pragma unroll
        for (int j = 0; j < 13; j++) {
            if (j < jcount) {
                #pragma unroll
                for (int c = 0; c < 4; c++)
                    acc[j][c] = acc[j][c] > 0.f ? acc[j][c] : ALPHA * acc[j][c];
            }
        }
    }
    float inv_lo = 1.f, inv_hi = 1.f;
    if (NORM) {
        float slo = 0.f, shi = 0.f;
        #pragma unroll
        for (int j = 0; j < 13; j++) {
            if (j < jcount) {
                slo = fmaf(acc[j][0], acc[j][0], slo);
                slo = fmaf(acc[j][1], acc[j][1], slo);
                shi = fmaf(acc[j][2], acc[j][2], shi);
                shi = fmaf(acc[j][3], acc[j][3], shi);
            }
        }
        #pragma unroll
        for (int o = 1; o <= 2; o <<= 1) {
            slo += __shfl_xor_sync(0xffffffffu, slo, o);
            shi += __shfl_xor_sync(0xffffffffu, shi, o);
        }
        if (tig == 0) {
            ssum[wm * 16 + grp][wn] = slo;
            ssum[wm * 16 + grp + 8][wn] = shi;
        }
        __syncthreads();
        float tlo = ssum[wm * 16 + grp][0] + ssum[wm * 16 + grp][1];
        float thi = ssum[wm * 16 + grp + 8][0] + ssum[wm * 16 + grp + 8][1];
        inv_lo = 1.0f / fmaxf(sqrtf(tlo), EPSN);
        inv_hi = 1.0f / fmaxf(sqrtf(thi), EPSN);
    }

    const int row_lo = r0 + wm * 16 + grp;
    const int row_hi = row_lo + 8;
    #pragma unroll
    for (int j = 0; j < 13; j++) {
        if (j < jcount) {
            int col = (jbase + j) * 8 + tig * 2;
            float o0 = acc[j][0] * inv_lo, o1 = acc[j][1] * inv_lo;
            float o2 = acc[j][2] * inv_hi, o3 = acc[j][3] * inv_hi;
            if (HALF_OUT) {
                __half* C = (__half*)Cv;
                __half2 plo = __float22half2_rn(make_float2(o0, o1));
                __half2 phi = __float22half2_rn(make_float2(o2, o3));
                if (row_lo < nRows) *(__half2*)&C[(long long)row_lo * 200 + col] = plo;
                if (row_hi < nRows) *(__half2*)&C[(long long)row_hi * 200 + col] = phi;
            } else {
                float* C = (float*)Cv;
                if (row_lo < nRows) *(float2*)&C[(long long)row_lo * 200 + col] = make_float2(o0, o1);
                if (row_hi < nRows) *(float2*)&C[(long long)row_hi * 200 + col] = make_float2(o2, o3);
            }
        }
    }
}

// ---------------- launch ----------------
extern "C" void kernel_launch(void* const* d_in, const int* in_sizes, int n_in,
                              void* d_out, int out_size) {
    const float* emb = (const float*)d_in[0];        // [N_TOT, 100]
    const float* W1  = (const float*)d_in[1];        // [100, 200]
    const float* W2  = (const float*)d_in[2];        // [200, 200]
    const void*  ei  = d_in[3];                      // [2, E]
    const float* ev  = (const float*)d_in[4];        // [E]
    float* out = (float*)d_out;                      // [N_TOT, 200]

    __half* embh; cudaGetSymbolAddress((void**)&embh, g_embh);
    __half* w1t;  cudaGetSymbolAddress((void**)&w1t, g_w1t);
    __half* w2t;  cudaGetSymbolAddress((void**)&w2t, g_w2t);
    __half* bufh; cudaGetSymbolAddress((void**)&bufh, g_bufh);
    __half* h1h;  cudaGetSymbolAddress((void**)&h1h, g_h1h);

    // CSR build: hist (ranks, 8 edges/thr) -> scan (+conversions) -> scatter
    hist_kernel<<<(E_NUM / 8 + 255) / 256, 256>>>(ei);
    scan_kernel<<<SCAN_NB, SCAN_BLK>>>((const float2*)emb, W1, W2);
    scatter_kernel<<<(E_NUM / 8 + 255) / 256, 256>>>(ei, ev);

    int ggrid = (N_TOT + 63) / 64;

    // Layer 1: agg(emb fp16) -> fp16; gemm1(+leaky) -> h1 fp16
    agg1_kernel<<<(N_TOT + 7) / 8, 256>>>((const uint2*)embh, bufh, N_TOT);
    gemm_f16_kernel<D_IN, 120, true, false, true><<<ggrid, 256>>>(bufh, w1t, h1h, N_TOT);

    // Layer 2: agg(h1 fp16) -> fp16; gemm2(+leaky+norm) -> d_out fp32
    aggH_kernel<<<(N_TOT + 7) / 8, 256>>>((const uint4*)h1h, (uint4*)bufh, N_TOT);
    gemm_f16_kernel<D_OUT, 200, true, true, false><<<ggrid, 256>>>(bufh, w2t, out, N_TOT);
}

// round 17
// speedup vs baseline: 1.0245x; 1.0145x over previous
#include <cuda_runtime.h>
#include <cuda_fp16.h>
#include <cstdint>
#include <utility>

#define N_ENT 50000
#define N_REL 500
#define N_TOT (N_ENT + N_REL)   // 50500
#define E_NUM 800000
#define D_IN  100
#define D_OUT 200
#define ALPHA 0.2f
#define EPSN  1e-12f

#define SCAN_BLK 1024
#define SCAN_NB  ((N_TOT + SCAN_BLK - 1) / SCAN_BLK)   // 50

// ---------------- scratch (device globals; zero-initialized at load) -------
__device__ __half g_embh[N_TOT * D_IN];   // fp16 embeddings
__device__ __half g_w1t[D_OUT * D_IN];    // W1^T fp16: [200][100]
__device__ __half g_w2t[D_OUT * D_OUT];   // W2^T fp16: [200][200]
__device__ __half g_bufh[N_TOT * D_OUT];  // agg1 out [N,100] / aggH out [N,200]
__device__ __half g_h1h[N_TOT * D_OUT];   // layer-1 output [N,200]
__device__ int    g_counts[N_TOT];        // zeroed at load; re-zeroed by scan
__device__ int    g_starts[N_TOT + 1];
__device__ int    g_rank[E_NUM];          // edge rank within its dst bucket
__device__ int    g_bsum[SCAN_NB];
__device__ int    g_flag[SCAN_NB];        // lookback flags; reset by hist blk0
__device__ int2   g_edge[E_NUM];          // dst-sorted (src, val_bits fp32)

// ---------------- PDL helpers ----------------
__device__ __forceinline__ void pdl_wait() {
    asm volatile("griddepcontrol.wait;" ::: "memory");
}
__device__ __forceinline__ void pdl_trigger() {
    asm volatile("griddepcontrol.launch_dependents;" ::: "memory");
}

// ---------------- helpers ----------------
__device__ __forceinline__ int detect_is64_block(const int* ei_words) {
    __shared__ int s_is64;
    if (threadIdx.x == 0) {
        int f = 1;
        #pragma unroll 8
        for (int j = 1; j < 256; j += 2)
            if (ei_words[j] != 0) f = 0;
        s_is64 = f;
    }
    __syncthreads();
    return s_is64;
}
__device__ __forceinline__ void mma_f16_k16(
    float& d0, float& d1, float& d2, float& d3,
    unsigned a0, unsigned a1, unsigned a2, unsigned a3,
    unsigned b0, unsigned b1,
    float c0, float c1, float c2, float c3) {
    asm("mma.sync.aligned.m16n8k16.row.col.f32.f16.f16.f32 "
        "{%0,%1,%2,%3},{%4,%5,%6,%7},{%8,%9},{%10,%11,%12,%13};"
        : "=f"(d0), "=f"(d1), "=f"(d2), "=f"(d3)
        : "r"(a0), "r"(a1), "r"(a2), "r"(a3), "r"(b0), "r"(b1),
          "f"(c0), "f"(c1), "f"(c2), "f"(c3));
}
__device__ __forceinline__ void mma_f16_k8(
    float& d0, float& d1, float& d2, float& d3,
    unsigned a0, unsigned a1, unsigned b0,
    float c0, float c1, float c2, float c3) {
    asm("mma.sync.aligned.m16n8k8.row.col.f32.f16.f16.f32 "
        "{%0,%1,%2,%3},{%4,%5},{%6},{%7,%8,%9,%10};"
        : "=f"(d0), "=f"(d1), "=f"(d2), "=f"(d3)
        : "r"(a0), "r"(a1), "r"(b0),
          "f"(c0), "f"(c1), "f"(c2), "f"(c3));
}
__device__ __forceinline__ void load_idx8(const void* ei, long long base, int e8,
                                          int is64, int d[8]) {
    if (is64) {
        const longlong2* p = (const longlong2*)ei;
        long long off = (base + 8LL * e8) >> 1;
        longlong2 a = __ldg(&p[off]);
        longlong2 b = __ldg(&p[off + 1]);
        longlong2 c = __ldg(&p[off + 2]);
        longlong2 e = __ldg(&p[off + 3]);
        d[0] = (int)a.x; d[1] = (int)a.y; d[2] = (int)b.x; d[3] = (int)b.y;
        d[4] = (int)c.x; d[5] = (int)c.y; d[6] = (int)e.x; d[7] = (int)e.y;
    } else {
        const int4* p = (const int4*)ei;
        long long off = (base + 8LL * e8) >> 2;
        int4 a = __ldg(&p[off]);
        int4 b = __ldg(&p[off + 1]);
        d[0] = a.x; d[1] = a.y; d[2] = a.z; d[3] = a.w;
        d[4] = b.x; d[5] = b.y; d[6] = b.z; d[7] = b.w;
    }
}

// ---------------- hist: 8 edges/thread; count + record per-edge rank -------
__global__ void __launch_bounds__(256)
hist_kernel(const void* __restrict__ ei) {
    pdl_wait();
    int is64 = detect_is64_block((const int*)ei);
    if (blockIdx.x == 0 && threadIdx.x < SCAN_NB) g_flag[threadIdx.x] = 0;
    int e8 = blockIdx.x * blockDim.x + threadIdx.x;
    if (e8 < E_NUM / 8) {
        int d[8];
        load_idx8(ei, E_NUM, e8, is64, d);
        int rk[8];
        #pragma unroll
        for (int q = 0; q < 8; q++)
            rk[q] = atomicAdd(&g_counts[d[q]], 1);
        int4* rp = (int4*)g_rank;
        rp[e8 * 2]     = make_int4(rk[0], rk[1], rk[2], rk[3]);
        rp[e8 * 2 + 1] = make_int4(rk[4], rk[5], rk[6], rk[7]);
    }
    pdl_trigger();
}

// ------- scan (decoupled lookback) + fp16 conversions (emb, W1^T, W2^T) ----
__global__ void __launch_bounds__(SCAN_BLK)
scan_kernel(const float2* __restrict__ emb, const float* __restrict__ W1,
            const float* __restrict__ W2) {
    pdl_wait();
    __shared__ int woff[32];
    __shared__ int s_off[2];
    const int tid = threadIdx.x;
    const int lane = tid & 31;
    const int wid = tid >> 5;
    const int b = blockIdx.x;
    const int i = b * SCAN_BLK + tid;

    int v = (i < N_TOT) ? g_counts[i] : 0;
    if (i < N_TOT) g_counts[i] = 0;        // re-zero for next replay

    int incl = v;
    #pragma unroll
    for (int o = 1; o < 32; o <<= 1) {
        int t = __shfl_up_sync(0xffffffffu, incl, o);
        if (lane >= o) incl += t;
    }
    if (lane == 31) woff[wid] = incl;
    __syncthreads();
    if (wid == 0) {
        int w = woff[lane];
        int wincl = w;
        #pragma unroll
        for (int o = 1; o < 32; o <<= 1) {
            int t = __shfl_up_sync(0xffffffffu, wincl, o);
            if (lane >= o) wincl += t;
        }
        woff[lane] = wincl - w;
        if (lane == 31) {
            g_bsum[b] = wincl;
            __threadfence();
            atomicExch(&g_flag[b], 1);
        }
    }
    __syncthreads();

    if (tid < 64) {
        int offv = 0;
        if (tid < b) {
            while (atomicAdd(&g_flag[tid], 0) == 0) { }
            __threadfence();
            offv = g_bsum[tid];
        }
        #pragma unroll
        for (int o = 16; o; o >>= 1) offv += __shfl_down_sync(0xffffffffu, offv, o);
        if ((tid & 31) == 0) s_off[tid >> 5] = offv;
    }
    __syncthreads();
    int off = s_off[0] + s_off[1];

    if (i < N_TOT) g_starts[i] = off + woff[wid] + (incl - v);
    if (b == SCAN_NB - 1 && tid == 0)
        g_starts[N_TOT] = off + g_bsum[b];

    // streaming fp16 conversions on the mostly-idle chip
    const int gtid = b * SCAN_BLK + tid;
    const int stride = SCAN_NB * SCAN_BLK;
    __half2* dst = (__half2*)g_embh;
    const int total2 = N_TOT * D_IN / 2;
    for (int k = gtid; k < total2; k += stride)
        dst[k] = __float22half2_rn(__ldg(&emb[k]));
    for (int k = gtid; k < D_IN * D_OUT; k += stride) {
        int kk = k / D_OUT, n = k % D_OUT;
        g_w1t[n * D_IN + kk] = __float2half_rn(__ldg(&W1[k]));
    }
    for (int k = gtid; k < D_OUT * D_OUT; k += stride) {
        int kk = k / D_OUT, n = k % D_OUT;
        g_w2t[n * D_OUT + kk] = __float2half_rn(__ldg(&W2[k]));
    }
    pdl_trigger();
}

// ---------------- scatter: 8 edges/thread, atomic-free via ranks -----------
__global__ void __launch_bounds__(256)
scatter_kernel(const void* __restrict__ ei, const float* __restrict__ ev) {
    pdl_wait();
    int is64 = detect_is64_block((const int*)ei);
    int e8 = blockIdx.x * blockDim.x + threadIdx.x;
    if (e8 < E_NUM / 8) {
        int s[8], d[8];
        load_idx8(ei, 0, e8, is64, s);
        load_idx8(ei, E_NUM, e8, is64, d);
        const int4* rp = (const int4*)g_rank;
        int4 ra = __ldg(&rp[e8 * 2]);
        int4 rb = __ldg(&rp[e8 * 2 + 1]);
        int rk[8] = {ra.x, ra.y, ra.z, ra.w, rb.x, rb.y, rb.z, rb.w};
        float4 va = __ldg(&((const float4*)ev)[e8 * 2]);
        float4 vb = __ldg(&((const float4*)ev)[e8 * 2 + 1]);
        float vv[8] = {va.x, va.y, va.z, va.w, vb.x, vb.y, vb.z, vb.w};
        int pos[8];
        #pragma unroll
        for (int q = 0; q < 8; q++)
            pos[q] = __ldg(&g_starts[d[q]]) + rk[q];
        #pragma unroll
        for (int q = 0; q < 8; q++)
            g_edge[pos[q]] = make_int2(s[q], __float_as_int(vv[q]));
    }
    pdl_trigger();
}

// ---------------- agg1: bufh[r,0:100] = fp16( sum embh[src]*val ) ----------
__global__ void __launch_bounds__(256)
agg1_kernel(const uint2* __restrict__ h, __half* __restrict__ out, int nRows) {
    pdl_wait();
    const int g = threadIdx.x >> 5;
    const int lane = threadIdx.x & 31;
    const int r = blockIdx.x * 8 + g;
    if (r < nRows) {
        const bool act = lane < 25;
        const int beg = g_starts[r];
        const int end = g_starts[r + 1];

        float acc[4] = {0.f, 0.f, 0.f, 0.f};
        int i = beg;
        for (; i + 3 < end; i += 4) {
            int2 e0 = __ldg(&g_edge[i]),     e1 = __ldg(&g_edge[i + 1]);
            int2 e2 = __ldg(&g_edge[i + 2]), e3 = __ldg(&g_edge[i + 3]);
            if (act) {
                uint2 u0 = __ldg(&h[(long long)e0.x * 25 + lane]);
                uint2 u1 = __ldg(&h[(long long)e1.x * 25 + lane]);
                uint2 u2 = __ldg(&h[(long long)e2.x * 25 + lane]);
                uint2 u3 = __ldg(&h[(long long)e3.x * 25 + lane]);
                float v0 = __int_as_float(e0.y), v1 = __int_as_float(e1.y);
                float v2 = __int_as_float(e2.y), v3 = __int_as_float(e3.y);
                float2 a0 = __half22float2(*(const __half2*)&u0.x);
                float2 b0 = __half22float2(*(const __half2*)&u0.y);
                float2 a1 = __half22float2(*(const __half2*)&u1.x);
                float2 b1 = __half22float2(*(const __half2*)&u1.y);
                float2 a2 = __half22float2(*(const __half2*)&u2.x);
                float2 b2 = __half22float2(*(const __half2*)&u2.y);
                float2 a3 = __half22float2(*(const __half2*)&u3.x);
                float2 b3 = __half22float2(*(const __half2*)&u3.y);
                acc[0] = fmaf(a0.x, v0, acc[0]); acc[1] = fmaf(a0.y, v0, acc[1]);
                acc[2] = fmaf(b0.x, v0, acc[2]); acc[3] = fmaf(b0.y, v0, acc[3]);
                acc[0] = fmaf(a1.x, v1, acc[0]); acc[1] = fmaf(a1.y, v1, acc[1]);
                acc[2] = fmaf(b1.x, v1, acc[2]); acc[3] = fmaf(b1.y, v1, acc[3]);
                acc[0] = fmaf(a2.x, v2, acc[0]); acc[1] = fmaf(a2.y, v2, acc[1]);
                acc[2] = fmaf(b2.x, v2, acc[2]); acc[3] = fmaf(b2.y, v2, acc[3]);
                acc[0] = fmaf(a3.x, v3, acc[0]); acc[1] = fmaf(a3.y, v3, acc[1]);
                acc[2] = fmaf(b3.x, v3, acc[2]); acc[3] = fmaf(b3.y, v3, acc[3]);
            }
        }
        for (; i < end; i++) {
            int2 e0 = __ldg(&g_edge[i]);
            if (act) {
                float v0 = __int_as_float(e0.y);
                uint2 u0 = __ldg(&h[(long long)e0.x * 25 + lane]);
                float2 a0 = __half22float2(*(const __half2*)&u0.x);
                float2 b0 = __half22float2(*(const __half2*)&u0.y);
                acc[0] = fmaf(a0.x, v0, acc[0]); acc[1] = fmaf(a0.y, v0, acc[1]);
                acc[2] = fmaf(b0.x, v0, acc[2]); acc[3] = fmaf(b0.y, v0, acc[3]);
            }
        }
        if (act) {
            __half2 h0 = __float22half2_rn(make_float2(acc[0], acc[1]));
            __half2 h1 = __float22half2_rn(make_float2(acc[2], acc[3]));
            uint2 u = make_uint2(*(unsigned*)&h0, *(unsigned*)&h1);
            *(uint2*)&out[(long long)r * 100 + lane * 4] = u;
        }
    }
    pdl_trigger();
}

// ---------------- aggH: bufh[r,0:200] = fp16( sum h1h[src]*val ) -----------
__global__ void __launch_bounds__(256)
aggH_kernel(const uint4* __restrict__ h, uint4* __restrict__ out, int nRows) {
    pdl_wait();
    const int g = threadIdx.x >> 5;
    const int lane = threadIdx.x & 31;
    const int r = blockIdx.x * 8 + g;
    if (r < nRows) {
        const bool act = lane < 25;
        const int beg = g_starts[r];
        const int end = g_starts[r + 1];

        float acc[8];
        #pragma unroll
        for (int c = 0; c < 8; c++) acc[c] = 0.f;

        int i = beg;
        for (; i + 3 < end; i += 4) {
            int2 e0 = __ldg(&g_edge[i]),     e1 = __ldg(&g_edge[i + 1]);
            int2 e2 = __ldg(&g_edge[i + 2]), e3 = __ldg(&g_edge[i + 3]);
            if (act) {
                uint4 u0 = __ldg(&h[(long long)e0.x * 25 + lane]);
                uint4 u1 = __ldg(&h[(long long)e1.x * 25 + lane]);
                uint4 u2 = __ldg(&h[(long long)e2.x * 25 + lane]);
                uint4 u3 = __ldg(&h[(long long)e3.x * 25 + lane]);
                float v0 = __int_as_float(e0.y), v1 = __int_as_float(e1.y);
                float v2 = __int_as_float(e2.y), v3 = __int_as_float(e3.y);
                const unsigned* w0 = &u0.x;
                const unsigned* w1 = &u1.x;
                const unsigned* w2 = &u2.x;
                const unsigned* w3 = &u3.x;
                #pragma unroll
                for (int q = 0; q < 4; q++) {
                    float2 f0 = __half22float2(*(const __half2*)&w0[q]);
                    float2 f1 = __half22float2(*(const __half2*)&w1[q]);
                    float2 f2 = __half22float2(*(const __half2*)&w2[q]);
                    float2 f3 = __half22float2(*(const __half2*)&w3[q]);
                    acc[q * 2]     = fmaf(f0.x, v0, acc[q * 2]);
                    acc[q * 2 + 1] = fmaf(f0.y, v0, acc[q * 2 + 1]);
                    acc[q * 2]     = fmaf(f1.x, v1, acc[q * 2]);
                    acc[q * 2 + 1] = fmaf(f1.y, v1, acc[q * 2 + 1]);
                    acc[q * 2]     = fmaf(f2.x, v2, acc[q * 2]);
                    acc[q * 2 + 1] = fmaf(f2.y, v2, acc[q * 2 + 1]);
                    acc[q * 2]     = fmaf(f3.x, v3, acc[q * 2]);
                    acc[q * 2 + 1] = fmaf(f3.y, v3, acc[q * 2 + 1]);
                }
            }
        }
        for (; i < end; i++) {
            int2 e0 = __ldg(&g_edge[i]);
            if (act) {
                float v0 = __int_as_float(e0.y);
                uint4 u0 = __ldg(&h[(long long)e0.x * 25 + lane]);
                const unsigned* w0 = &u0.x;
                #pragma unroll
                for (int q = 0; q < 4; q++) {
                    float2 f0 = __half22float2(*(const __half2*)&w0[q]);
                    acc[q * 2]     = fmaf(f0.x, v0, acc[q * 2]);
                    acc[q * 2 + 1] = fmaf(f0.y, v0, acc[q * 2 + 1]);
                }
            }
        }
        if (act) {
            uint4 u;
            __half2 p0 = __float22half2_rn(make_float2(acc[0], acc[1]));
            __half2 p1 = __float22half2_rn(make_float2(acc[2], acc[3]));
            __half2 p2 = __float22half2_rn(make_float2(acc[4], acc[5]));
            __half2 p3 = __float22half2_rn(make_float2(acc[6], acc[7]));
            u.x = *(unsigned*)&p0; u.y = *(unsigned*)&p1;
            u.z = *(unsigned*)&p2; u.w = *(unsigned*)&p3;
            out[(long long)r * 25 + lane] = u;
        }
    }
    pdl_trigger();
}

// ---------------- fp16 HMMA GEMM: C = postproc(A_half @ Wt_half^T) ---------
#define CK 40
#define APAD 52
template <int K, int KP, bool LEAKY, bool NORM, bool HALF_OUT>
__global__ void __launch_bounds__(256)
gemm_f16_kernel(const __half* __restrict__ A, const __half* __restrict__ Wt,
                void* __restrict__ Cv, int nRows) {
    pdl_wait();
    __shared__ __half a_s[64][APAD];
    __shared__ __half w_s[200][APAD];
    __shared__ float ssum[64][2];
    const int tid = threadIdx.x;
    const int wid = tid >> 5;
    const int lane = tid & 31;
    const int grp = lane >> 2;
    const int tig = lane & 3;
    const int wm = wid & 3;
    const int wn = wid >> 2;
    const int jbase = wn ? 13 : 0;
    const int jcount = wn ? 12 : 13;
    const int r0 = blockIdx.x * 64;

    float acc[13][4];
    #pragma unroll
    for (int j = 0; j < 13; j++)
        #pragma unroll
        for (int c = 0; c < 4; c++) acc[j][c] = 0.f;

    #pragma unroll
    for (int ch = 0; ch < KP / CK; ch++) {
        const int k0 = ch * CK;
        #pragma unroll
        for (int i = 0; i < 3; i++) {
            int idx4 = tid + i * 256;
            if (idx4 < 640) {
                int row = idx4 / 10;
                int q = idx4 % 10;
                int gr = r0 + row;
                uint2 u = make_uint2(0u, 0u);
                if (gr < nRows && k0 + q * 4 < K)
                    u = *(const uint2*)&A[(long long)gr * K + k0 + q * 4];
                *(uint2*)&a_s[row][q * 4] = u;
            }
        }
        #pragma unroll
        for (int i = 0; i < 8; i++) {
            int idx4 = tid + i * 256;
            if (idx4 < 2000) {
                int n = idx4 / 10;
                int q = idx4 % 10;
                uint2 u = make_uint2(0u, 0u);
                if (k0 + q * 4 < K)
                    u = *(const uint2*)&Wt[(long long)n * K + k0 + q * 4];
                *(uint2*)&w_s[n][q * 4] = u;
            }
        }
        __syncthreads();

        const int arow = wm * 16 + grp;
        #pragma unroll
        for (int ks = 0; ks < 2; ks++) {
            const int kk = ks * 16;
            unsigned a0 = *(const unsigned*)&a_s[arow][kk + 2 * tig];
            unsigned a1 = *(const unsigned*)&a_s[arow + 8][kk + 2 * tig];
            unsigned a2 = *(const unsigned*)&a_s[arow][kk + 2 * tig + 8];
            unsigned a3 = *(const unsigned*)&a_s[arow + 8][kk + 2 * tig + 8];
            #pragma unroll
            for (int j = 0; j < 13; j++) {
                if (j < jcount) {
                    int n = (jbase + j) * 8 + grp;
                    unsigned b0 = *(const unsigned*)&w_s[n][kk + 2 * tig];
                    unsigned b1 = *(const unsigned*)&w_s[n][kk + 2 * tig + 8];
                    mma_f16_k16(acc[j][0], acc[j][1], acc[j][2], acc[j][3],
                                a0, a1, a2, a3, b0, b1,
                                acc[j][0], acc[j][1], acc[j][2], acc[j][3]);
                }
            }
        }
        {
            unsigned a0 = *(const unsigned*)&a_s[arow][32 + 2 * tig];
            unsigned a1 = *(const unsigned*)&a_s[arow + 8][32 + 2 * tig];
            #pragma unroll
            for (int j = 0; j < 13; j++) {
                if (j < jcount) {
                    int n = (jbase + j) * 8 + grp;
                    unsigned b0 = *(const unsigned*)&w_s[n][32 + 2 * tig];
                    mma_f16_k8(acc[j][0], acc[j][1], acc[j][2], acc[j][3],
                               a0, a1, b0,
                               acc[j][0], acc[j][1], acc[j][2], acc[j][3]);
                }
            }
        }
        __syncthreads();
    }

    if (LEAKY || NORM) {
        #pragma unroll
        for (int j = 0; j < 13; j++) {
            if (j < jcount) {
                #pragma unroll
                for (int c = 0; c < 4; c++)
                    acc[j][c] = acc[j][c] > 0.f ? acc[j][c] : ALPHA * acc[j][c];
            }
        }
    }
    float inv_lo = 1.f, inv_hi = 1.f;
    if (NORM) {
        float slo = 0.f, shi = 0.f;
        #pragma unroll
        for (int j = 0; j < 13; j++) {
            if (j < jcount) {
                slo = fmaf(acc[j][0], acc[j][0], slo);
                slo = fmaf(acc[j][1], acc[j][1], slo);
                shi = fmaf(acc[j][2], acc[j][2], shi);
                shi = fmaf(acc[j][3], acc[j][3], shi);
            }
        }
        #pragma unroll
        for (int o = 1; o <= 2; o <<= 1) {
            slo += __shfl_xor_sync(0xffffffffu, slo, o);
            shi += __shfl_xor_sync(0xffffffffu, shi, o);
        }
        if (tig == 0) {
            ssum[wm * 16 + grp][wn] = slo;
            ssum[wm * 16 + grp + 8][wn] = shi;
        }
        __syncthreads();
        float tlo = ssum[wm * 16 + grp][0] + ssum[wm * 16 + grp][1];
        float thi = ssum[wm * 16 + grp + 8][0] + ssum[wm * 16 + grp + 8][1];
        inv_lo = 1.0f / fmaxf(sqrtf(tlo), EPSN);
        inv_hi = 1.0f / fmaxf(sqrtf(thi), EPSN);
    }

    const int row_lo = r0 + wm * 16 + grp;
    const int row_hi = row_lo + 8;
    #pragma unroll
    for (int j = 0; j < 13; j++) {
        if (j < jcount) {
            int col = (jbase + j) * 8 + tig * 2;
            float o0 = acc[j][0] * inv_lo, o1 = acc[j][1] * inv_lo;
            float o2 = acc[j][2] * inv_hi, o3 = acc[j][3] * inv_hi;
            if (HALF_OUT) {
                __half* C = (__half*)Cv;
                __half2 plo = __float22half2_rn(make_float2(o0, o1));
                __half2 phi = __float22half2_rn(make_float2(o2, o3));
                if (row_lo < nRows) *(__half2*)&C[(long long)row_lo * 200 + col] = plo;
                if (row_hi < nRows) *(__half2*)&C[(long long)row_hi * 200 + col] = phi;
            } else {
                float* C = (float*)Cv;
                if (row_lo < nRows) *(float2*)&C[(long long)row_lo * 200 + col] = make_float2(o0, o1);
                if (row_hi < nRows) *(float2*)&C[(long long)row_hi * 200 + col] = make_float2(o2, o3);
            }
        }
    }
    pdl_trigger();
}

// ---------------- PDL launch helper ----------------
template <typename F, typename... Args>
static inline void launch_pdl(F kern, dim3 grid, dim3 block, Args... args) {
    cudaLaunchConfig_t cfg = {};
    cfg.gridDim = grid;
    cfg.blockDim = block;
    cudaLaunchAttribute attrs[1];
    attrs[0].id = cudaLaunchAttributeProgrammaticStreamSerialization;
    attrs[0].val.programmaticStreamSerializationAllowed = 1;
    cfg.attrs = attrs;
    cfg.numAttrs = 1;
    cudaLaunchKernelEx(&cfg, kern, args...);
}

// ---------------- launch ----------------
extern "C" void kernel_launch(void* const* d_in, const int* in_sizes, int n_in,
                              void* d_out, int out_size) {
    const float* emb = (const float*)d_in[0];        // [N_TOT, 100]
    const float* W1  = (const float*)d_in[1];        // [100, 200]
    const float* W2  = (const float*)d_in[2];        // [200, 200]
    const void*  ei  = d_in[3];                      // [2, E]
    const float* ev  = (const float*)d_in[4];        // [E]
    float* out = (float*)d_out;                      // [N_TOT, 200]

    __half* embh; cudaGetSymbolAddress((void**)&embh, g_embh);
    __half* w1t;  cudaGetSymbolAddress((void**)&w1t, g_w1t);
    __half* w2t;  cudaGetSymbolAddress((void**)&w2t, g_w2t);
    __half* bufh; cudaGetSymbolAddress((void**)&bufh, g_bufh);
    __half* h1h;  cudaGetSymbolAddress((void**)&h1h, g_h1h);

    const dim3 b256(256);
    // CSR build: hist (ranks) -> scan (+conversions) -> atomic-free scatter
    launch_pdl(hist_kernel, dim3((E_NUM / 8 + 255) / 256), b256, ei);
    launch_pdl(scan_kernel, dim3(SCAN_NB), dim3(SCAN_BLK),
               (const float2*)emb, W1, W2);
    launch_pdl(scatter_kernel, dim3((E_NUM / 8 + 255) / 256), b256, ei, ev);

    int ggrid = (N_TOT + 63) / 64;

    // Layer 1: agg(emb fp16) -> fp16; gemm1(+leaky) -> h1 fp16
    launch_pdl(agg1_kernel, dim3((N_TOT + 7) / 8), b256,
               (const uint2*)embh, bufh, N_TOT);
    launch_pdl(gemm_f16_kernel<D_IN, 120, true, false, true>, dim3(ggrid), b256,
               (const __half*)bufh, (const __half*)w1t, (void*)h1h, N_TOT);

    // Layer 2: agg(h1 fp16) -> fp16; gemm2(+leaky+norm) -> d_out fp32
    launch_pdl(aggH_kernel, dim3((N_TOT + 7) / 8), b256,
               (const uint4*)h1h, (uint4*)bufh, N_TOT);
    launch_pdl(gemm_f16_kernel<D_OUT, 200, true, true, false>, dim3(ggrid), b256,
               (const __half*)bufh, (const __half*)w2t, (void*)out, N_TOT);
}